// round 8
// baseline (speedup 1.0000x reference)
#include <cuda_runtime.h>
#include <cuda_bf16.h>
#include <math.h>

#define T  8192
#define E  20
#define H1 30
#define H2 50
#define HL 300
#define NT 50
#define G1 (4*H1)   // 120
#define G2 (4*H2)   // 200
#define D2 (2*H1)   // 60
#define D3 (2*H2)   // 100

// ---- scratch (no allocations allowed) ----
// gx layout: [t][unit][q] with q in (i,g,f,o) order, sigmoid rows pre-scaled by 0.5
__device__ float g_gx_fw1[T*G1];
__device__ float g_gx_bw1[T*G1];
__device__ float g_l1[T*D2];
__device__ float g_gx_fw2[T*G2];
__device__ float g_gx_bw2[T*G2];
__device__ float g_l2[T*D3];

typedef unsigned long long u64;

__device__ __forceinline__ u64 pk(float lo, float hi) {
    u64 r; asm("mov.b64 %0, {%1, %2};" : "=l"(r) : "f"(lo), "f"(hi)); return r;
}
__device__ __forceinline__ void upk(u64 v, float& lo, float& hi) {
    asm("mov.b64 {%0, %1}, %2;" : "=f"(lo), "=f"(hi) : "l"(v));
}
__device__ __forceinline__ u64 ffma2(u64 a, u64 b, u64 c) {
    u64 d; asm("fma.rn.f32x2 %0, %1, %2, %3;" : "=l"(d) : "l"(a), "l"(b), "l"(c)); return d;
}
__device__ __forceinline__ u64 addx2(u64 a, u64 b) {
    u64 d; asm("add.rn.f32x2 %0, %1, %2;" : "=l"(d) : "l"(a), "l"(b)); return d;
}
__device__ __forceinline__ float tanh_ap(float x) {
    float y; asm("tanh.approx.f32 %0, %1;" : "=f"(y) : "f"(x)); return y;
}

// PyTorch gate index (i,f,g,o) -> lane nibble slot q in (i,g,f,o)
__device__ __host__ __forceinline__ int qslot(int gi) {
    return (gi == 0) ? 0 : (gi == 2) ? 1 : (gi == 1) ? 2 : 3;
}

// ============================================================
// Kernel 1: embedding gather + layer-1 input projections.
// dst[t*G1 + u*4 + qslot(gi)], pre-scaled x0.5 for sigmoid gates.
// ============================================================
__global__ void k_gx1(const int* __restrict__ x, const float* __restrict__ emb,
                      const float* __restrict__ WihF, const float* __restrict__ bF,
                      const float* __restrict__ WihB, const float* __restrict__ bB) {
    __shared__ float e[E];
    int t = blockIdx.x;
    int j = threadIdx.x;
    if (j < E) e[j] = emb[(size_t)x[t] * E + j];
    __syncthreads();
    if (j < G1) {
        int gi = j / H1, u = j % H1;
        float scl = (gi == 2) ? 1.f : 0.5f;
        float aF = bF[j], aB = bB[j];
        #pragma unroll
        for (int k = 0; k < E; k++) {
            float ev = e[k];
            aF += WihF[j*E + k] * ev;
            aB += WihB[j*E + k] * ev;
        }
        int q = qslot(gi);
        g_gx_fw1[t*G1 + u*4 + q] = aF * scl;
        g_gx_bw1[(T-1-t)*G1 + u*4 + q] = aB * scl;
    }
}

// ============================================================
// Shared step macro: one row per thread, (unit x gate) nibble
// layout, 3-shfl gate combine, one barrier per step.
// Outer scope: q, u, valid, c, mA, bA, outp, OUTSTRIDE symbols.
// ============================================================
#define UG_STEP(HR, HW, GC, NHALF, WP, OUTP, OUTSTRIDE, LQ) do {               \
    const ulonglong2* _h8 = (const ulonglong2*)(HR);                            \
    u64 _a0 = pk((GC), 0.f), _a1 = pk(0.f,0.f), _a2 = pk(0.f,0.f), _a3 = pk(0.f,0.f); \
    _Pragma("unroll")                                                           \
    for (int _kk = 0; _kk < (NHALF); _kk++) {                                   \
        ulonglong2 _hv = _h8[_kk];                                              \
        if ((_kk & 1) == 0) {                                                   \
            _a0 = ffma2((WP)[2*_kk],   _hv.x, _a0);                             \
            _a1 = ffma2((WP)[2*_kk+1], _hv.y, _a1);                             \
        } else {                                                                \
            _a2 = ffma2((WP)[2*_kk],   _hv.x, _a2);                             \
            _a3 = ffma2((WP)[2*_kk+1], _hv.y, _a3);                             \
        }                                                                       \
    }                                                                           \
    u64 _s = addx2(addx2(_a0, _a1), addx2(_a2, _a3));                           \
    float _lo, _hi; upk(_s, _lo, _hi);                                          \
    float _d = _lo + _hi;                                                       \
    float _A = fmaf(mA, tanh_ap(_d), bA);                                       \
    /* nibble: q0=i, q1=g, q2=f, q3=o */                                        \
    float _x1 = __shfl_xor_sync(0xFFFFFFFFu, _A, 1);                            \
    float _IG = _A * _x1;                     /* valid on q0,q1 */              \
    float _Fv = (LQ == 2) ? _A : _x1;          /* valid on q2,q3 */             \
    float _Ov = (LQ == 2) ? _x1 : _A;                                           \
    float _s1 = (LQ < 2) ? _IG : _Fv;                                           \
    float _s2 = (LQ < 2) ? _IG : _Ov;                                           \
    float _r1 = __shfl_xor_sync(0xFFFFFFFFu, _s1, 2);                           \
    float _r2 = __shfl_xor_sync(0xFFFFFFFFu, _s2, 2);                           \
    float _F  = (LQ < 2) ? _r1 : _Fv;                                           \
    float _O  = (LQ < 2) ? _r2 : _Ov;                                           \
    float _IGv = (LQ < 2) ? _IG : _r1;                                          \
    c = fmaf(_F, c, _IGv);                                                      \
    float _hn = _O * tanh_ap(c);                                                \
    if (valid) {                                                                \
        if (LQ == 0) (HW)[u] = _hn;                                             \
        else if (LQ == 1) *(OUTP) = _hn;                                        \
    }                                                                           \
    (OUTP) += (OUTSTRIDE);                                                      \
    __syncthreads();                                                            \
} while (0)

// ============================================================
// Kernel 2: layer-1 scan. 128 threads, thread = u*4+q (u<30).
// 16 FFMA2 per thread.
// ============================================================
__global__ void __launch_bounds__(128, 1) k_scan1(
    const float* __restrict__ WhhF, const float* __restrict__ h0F, const float* __restrict__ c0F,
    const float* __restrict__ WhhB, const float* __restrict__ h0B, const float* __restrict__ c0B) {
    const bool bw = (blockIdx.x == 1);
    const float* Whh = bw ? WhhB : WhhF;
    const float* h0  = bw ? h0B  : h0F;
    const float* c0  = bw ? c0B  : c0F;
    const float* gx  = bw ? g_gx_bw1 : g_gx_fw1;
    const int off = bw ? H1 : 0;

    __shared__ __align__(16) float h_sh[2][32];

    const int tid = threadIdx.x;
    const int u = tid >> 2;
    const int q = tid & 3;
    const bool valid = (u < H1);
    const int uu = valid ? u : 0;
    const int pyg = (q == 0) ? 0 : (q == 1) ? 2 : (q == 2) ? 1 : 3;
    const int row = pyg * H1 + uu;
    const float scl = (q == 1) ? 1.f : 0.5f;
    const float mA = scl;
    const float bA = (q == 1) ? 0.f : 0.5f;

    u64 wp[16];
    #pragma unroll
    for (int k = 0; k < 15; k++) {
        wp[k] = pk(valid ? scl*Whh[row*H1 + 2*k] : 0.f,
                   valid ? scl*Whh[row*H1 + 2*k + 1] : 0.f);
    }
    wp[15] = pk(0.f, 0.f);

    if (tid < 32) {
        h_sh[0][tid] = (tid < H1) ? h0[tid] : 0.f;
        h_sh[1][tid] = 0.f;
    }
    float c = valid ? c0[uu] : 0.f;

    const int gidx = uu*4 + q;
    float ga = gx[gidx];
    float gb = gx[G1 + gidx];
    const float* pre = gx + 2*G1 + gidx;
    float* outp = g_l1 + off + uu;
    __syncthreads();

    for (int t = 0; t < T - 2; t += 2) {
        { float gc = ga; ga = *pre; pre += G1;
          UG_STEP(h_sh[0], h_sh[1], gc, 8, wp, outp, D2, q); }
        { float gc = gb; gb = *pre; pre += G1;
          UG_STEP(h_sh[1], h_sh[0], gc, 8, wp, outp, D2, q); }
    }
    UG_STEP(h_sh[0], h_sh[1], ga, 8, wp, outp, D2, q);
    UG_STEP(h_sh[1], h_sh[0], gb, 8, wp, outp, D2, q);
}

// ============================================================
// Kernel 3: layer-2 input projections; writes [t][u][q] layout,
// sigmoid rows pre-scaled by 0.5.
// ============================================================
#define GX2_BLOCKS 64
__global__ void __launch_bounds__(256) k_gx2(
    const float* __restrict__ WihF, const float* __restrict__ bF,
    const float* __restrict__ WihB, const float* __restrict__ bB) {
    __shared__ float W[D2 * G2];   // [k][j]
    __shared__ float row[D2];
    const bool bw = (blockIdx.y == 1);
    const float* Wih = bw ? WihB : WihF;
    const float* b   = bw ? bB   : bF;
    float* dst = bw ? g_gx_bw2 : g_gx_fw2;

    for (int i = threadIdx.x; i < G2*D2; i += blockDim.x) {
        int r = i / D2, k = i % D2;
        W[k*G2 + r] = Wih[i];
    }
    int jme = threadIdx.x;
    int gi = (jme < G2) ? (jme / H2) : 0;
    int uj = (jme < G2) ? (jme % H2) : 0;
    float bias = (jme < G2) ? b[jme] : 0.f;
    float scl = (gi == 2) ? 1.f : 0.5f;
    int dpos = uj*4 + qslot(gi);
    __syncthreads();

    const int tpb = T / GX2_BLOCKS;
    const int t0 = blockIdx.x * tpb;
    for (int t = t0; t < t0 + tpb; t++) {
        int src = bw ? (T-1-t) : t;
        __syncthreads();
        for (int i = threadIdx.x; i < D2; i += blockDim.x) row[i] = g_l1[(size_t)src*D2 + i];
        __syncthreads();
        if (jme < G2) {
            float acc = bias;
            #pragma unroll
            for (int k = 0; k < D2; k++) acc += W[k*G2 + jme] * row[k];
            dst[(size_t)t*G2 + dpos] = acc * scl;
        }
    }
}

// ============================================================
// Kernel 4: layer-2 scan. 256 threads (8 warps, 2/SMSP),
// thread = u*4+q (u<50), 26 FFMA2 per thread.
// ============================================================
__global__ void __launch_bounds__(256, 1) k_scan2(
    const float* __restrict__ WhhF, const float* __restrict__ h0F, const float* __restrict__ c0F,
    const float* __restrict__ WhhB, const float* __restrict__ h0B, const float* __restrict__ c0B) {
    const bool bw = (blockIdx.x == 1);
    const float* Whh = bw ? WhhB : WhhF;
    const float* h0  = bw ? h0B  : h0F;
    const float* c0  = bw ? c0B  : c0F;
    const float* gx  = bw ? g_gx_bw2 : g_gx_fw2;
    const int off = bw ? H2 : 0;

    __shared__ __align__(16) float h_sh[2][56];

    const int tid = threadIdx.x;
    const int u = tid >> 2;
    const int q = tid & 3;
    const bool valid = (u < H2);
    const int uu = valid ? u : 0;
    const int pyg = (q == 0) ? 0 : (q == 1) ? 2 : (q == 2) ? 1 : 3;
    const int row = pyg * H2 + uu;
    const float scl = (q == 1) ? 1.f : 0.5f;
    const float mA = scl;
    const float bA = (q == 1) ? 0.f : 0.5f;

    u64 wp[26];
    #pragma unroll
    for (int k = 0; k < 25; k++) {
        wp[k] = pk(valid ? scl*Whh[row*H2 + 2*k] : 0.f,
                   valid ? scl*Whh[row*H2 + 2*k + 1] : 0.f);
    }
    wp[25] = pk(0.f, 0.f);

    if (tid < 56) {
        h_sh[0][tid] = (tid < H2) ? h0[tid] : 0.f;
        h_sh[1][tid] = 0.f;
    }
    float c = valid ? c0[uu] : 0.f;

    const int gidx = uu*4 + q;
    float ga = gx[gidx];
    float gb = gx[G2 + gidx];
    const float* pre = gx + 2*G2 + gidx;
    float* outp = g_l2 + off + uu;
    __syncthreads();

    for (int t = 0; t < T - 2; t += 2) {
        { float gc = ga; ga = *pre; pre += G2;
          UG_STEP(h_sh[0], h_sh[1], gc, 13, wp, outp, D3, q); }
        { float gc = gb; gb = *pre; pre += G2;
          UG_STEP(h_sh[1], h_sh[0], gc, 13, wp, outp, D3, q); }
    }
    UG_STEP(h_sh[0], h_sh[1], ga, 13, wp, outp, D3, q);
    UG_STEP(h_sh[1], h_sh[0], gb, 13, wp, outp, D3, q);
}

// ============================================================
// Kernel 5: final MLP (weights in dynamic shared).
// ============================================================
#define MLP_SMEM ((HL*D3 + NT*HL + D3 + HL) * 4)
__global__ void __launch_bounds__(320, 1) k_mlp(
    const float* __restrict__ W1, const float* __restrict__ b1,
    const float* __restrict__ W2, const float* __restrict__ b2,
    float* __restrict__ out) {
    extern __shared__ float sm[];
    float* W1s  = sm;
    float* W2s  = W1s + HL*D3;
    float* rowS = W2s + NT*HL;
    float* hidS = rowS + D3;

    int tid = threadIdx.x;
    for (int i = tid; i < HL*D3; i += blockDim.x) W1s[i] = W1[i];
    for (int i = tid; i < NT*HL; i += blockDim.x) W2s[i] = W2[i];
    __syncthreads();

    for (int t = blockIdx.x; t < T; t += gridDim.x) {
        if (tid < D3) rowS[tid] = g_l2[(size_t)t*D3 + tid];
        __syncthreads();
        if (tid < HL) {
            float acc = b1[tid];
            const float4* wr = (const float4*)(W1s + tid*D3);
            const float4* r4 = (const float4*)rowS;
            #pragma unroll
            for (int k = 0; k < D3/4; k++) {
                float4 wv = wr[k]; float4 rv = r4[k];
                acc += wv.x*rv.x + wv.y*rv.y + wv.z*rv.z + wv.w*rv.w;
            }
            hidS[tid] = tanhf(acc);
        }
        __syncthreads();
        if (tid < NT) {
            float acc = b2[tid];
            const float4* wr = (const float4*)(W2s + tid*HL);
            const float4* h4 = (const float4*)hidS;
            #pragma unroll
            for (int k = 0; k < HL/4; k++) {
                float4 wv = wr[k]; float4 hv = h4[k];
                acc += wv.x*hv.x + wv.y*hv.y + wv.z*hv.z + wv.w*hv.w;
            }
            out[(size_t)t*NT + tid] = acc;
        }
        __syncthreads();
    }
}

// ============================================================
// launch
// ============================================================
extern "C" void kernel_launch(void* const* d_in, const int* in_sizes, int n_in,
                              void* d_out, int out_size) {
    const int*   x   = (const int*)  d_in[0];
    const float* emb = (const float*)d_in[1];

    const float* fw1_Wih = (const float*)d_in[2];
    const float* fw1_Whh = (const float*)d_in[3];
    const float* fw1_b   = (const float*)d_in[4];
    const float* fw1_h0  = (const float*)d_in[5];
    const float* fw1_c0  = (const float*)d_in[6];

    const float* bw1_Wih = (const float*)d_in[7];
    const float* bw1_Whh = (const float*)d_in[8];
    const float* bw1_b   = (const float*)d_in[9];
    const float* bw1_h0  = (const float*)d_in[10];
    const float* bw1_c0  = (const float*)d_in[11];

    const float* fw2_Wih = (const float*)d_in[12];
    const float* fw2_Whh = (const float*)d_in[13];
    const float* fw2_b   = (const float*)d_in[14];
    const float* fw2_h0  = (const float*)d_in[15];
    const float* fw2_c0  = (const float*)d_in[16];

    const float* bw2_Wih = (const float*)d_in[17];
    const float* bw2_Whh = (const float*)d_in[18];
    const float* bw2_b   = (const float*)d_in[19];
    const float* bw2_h0  = (const float*)d_in[20];
    const float* bw2_c0  = (const float*)d_in[21];

    const float* lin1_W = (const float*)d_in[22];
    const float* lin1_b = (const float*)d_in[23];
    const float* lin2_W = (const float*)d_in[24];
    const float* lin2_b = (const float*)d_in[25];

    cudaFuncSetAttribute(k_mlp, cudaFuncAttributeMaxDynamicSharedMemorySize, MLP_SMEM);

    k_gx1<<<T, 128>>>(x, emb, fw1_Wih, fw1_b, bw1_Wih, bw1_b);
    k_scan1<<<2, 128>>>(fw1_Whh, fw1_h0, fw1_c0, bw1_Whh, bw1_h0, bw1_c0);
    k_gx2<<<dim3(GX2_BLOCKS, 2), 256>>>(fw2_Wih, fw2_b, bw2_Wih, bw2_b);
    k_scan2<<<2, 256>>>(fw2_Whh, fw2_h0, fw2_c0, bw2_Whh, bw2_h0, bw2_c0);
    k_mlp<<<148, 320, MLP_SMEM>>>(lin1_W, lin1_b, lin2_W, lin2_b, (float*)d_out);
}

// round 9
// speedup vs baseline: 1.6713x; 1.6713x over previous
#include <cuda_runtime.h>
#include <cuda_bf16.h>
#include <math.h>

#define T  8192
#define E  20
#define H1 30
#define H2 50
#define HL 300
#define NT 50
#define G1 (4*H1)   // 120
#define G2 (4*H2)   // 200
#define D2 (2*H1)   // 60
#define D3 (2*H2)   // 100

// ---- scratch (no allocations allowed) ----
// gx layout: [t][pair tid = 2u+p][2 slots]: p=0 -> (i_u, g_u), p=1 -> (f_u, o_u)
// sigmoid rows (i,f,o) pre-scaled by 0.5; g unscaled.
__device__ float g_gx_fw1[T*G1];
__device__ float g_gx_bw1[T*G1];
__device__ float g_l1[T*D2];
__device__ float g_gx_fw2[T*G2];
__device__ float g_gx_bw2[T*G2];
__device__ float g_l2[T*D3];

typedef unsigned long long u64;

__device__ __forceinline__ u64 pk(float lo, float hi) {
    u64 r; asm("mov.b64 %0, {%1, %2};" : "=l"(r) : "f"(lo), "f"(hi)); return r;
}
__device__ __forceinline__ void upk(u64 v, float& lo, float& hi) {
    asm("mov.b64 {%0, %1}, %2;" : "=f"(lo), "=f"(hi) : "l"(v));
}
__device__ __forceinline__ u64 ffma2(u64 a, u64 b, u64 c) {
    u64 d; asm("fma.rn.f32x2 %0, %1, %2, %3;" : "=l"(d) : "l"(a), "l"(b), "l"(c)); return d;
}
__device__ __forceinline__ u64 addx2(u64 a, u64 b) {
    u64 d; asm("add.rn.f32x2 %0, %1, %2;" : "=l"(d) : "l"(a), "l"(b)); return d;
}
__device__ __forceinline__ float tanh_ap(float x) {
    float y; asm("tanh.approx.f32 %0, %1;" : "=f"(y) : "f"(x)); return y;
}

// PyTorch gate gi (0=i,1=f,2=g,3=o) -> gx slot within unit nibble:
// i->0, g->1, f->2, o->3   (so pair p=0 reads slots {0,1}, p=1 reads {2,3})
__device__ __host__ __forceinline__ int gslot(int gi) {
    return (gi == 0) ? 0 : (gi == 2) ? 1 : (gi == 1) ? 2 : 3;
}

// ============================================================
// Kernel 1: embedding gather + layer-1 input projections.
// ============================================================
__global__ void k_gx1(const int* __restrict__ x, const float* __restrict__ emb,
                      const float* __restrict__ WihF, const float* __restrict__ bF,
                      const float* __restrict__ WihB, const float* __restrict__ bB) {
    __shared__ float e[E];
    int t = blockIdx.x;
    int j = threadIdx.x;
    if (j < E) e[j] = emb[(size_t)x[t] * E + j];
    __syncthreads();
    if (j < G1) {
        int gi = j / H1, u = j % H1;
        float scl = (gi == 2) ? 1.f : 0.5f;
        float aF = bF[j], aB = bB[j];
        #pragma unroll
        for (int k = 0; k < E; k++) {
            float ev = e[k];
            aF += WihF[j*E + k] * ev;
            aB += WihB[j*E + k] * ev;
        }
        int pos = u*4 + gslot(gi);
        g_gx_fw1[t*G1 + pos] = aF * scl;
        g_gx_bw1[(T-1-t)*G1 + pos] = aB * scl;
    }
}

// ============================================================
// Shared step macro, gate-pair layout {i,g}/{f,o}:
// lane tid=2u+p: p=0 rows (i_u, g_u), p=1 rows (f_u, o_u).
// A0 = sigmoid-form (i or f), A1 = (g: tanh | o: sigmoid-form).
// p=0 forms I*G locally; p=1 forms F*c locally; ONE fma after
// the two independent shfls. One __syncthreads per step.
// Outer scope: p, u, valid, c, m1, b1c, Z, outp, OUTS, wp0, wp1.
// ============================================================
#define PAIR_STEP(HR, HW, GV2, NHALF, PF) do {                                  \
    const ulonglong2* _h8 = (const ulonglong2*)(HR);                            \
    u64 _a0 = pk((GV2).x, 0.f), _a1 = Z, _a2 = Z, _a3 = Z;                      \
    u64 _b0 = pk((GV2).y, 0.f), _b1 = Z, _b2 = Z, _b3 = Z;                      \
    _Pragma("unroll")                                                           \
    for (int _kk = 0; _kk < (NHALF); _kk++) {                                   \
        ulonglong2 _hv = _h8[_kk];                                              \
        if ((_kk & 1) == 0) {                                                   \
            _a0 = ffma2(wp0[2*_kk],   _hv.x, _a0);                              \
            _a1 = ffma2(wp0[2*_kk+1], _hv.y, _a1);                              \
            _b0 = ffma2(wp1[2*_kk],   _hv.x, _b0);                              \
            _b1 = ffma2(wp1[2*_kk+1], _hv.y, _b1);                              \
        } else {                                                                \
            _a2 = ffma2(wp0[2*_kk],   _hv.x, _a2);                              \
            _a3 = ffma2(wp0[2*_kk+1], _hv.y, _a3);                              \
            _b2 = ffma2(wp1[2*_kk],   _hv.x, _b2);                              \
            _b3 = ffma2(wp1[2*_kk+1], _hv.y, _b3);                              \
        }                                                                       \
    }                                                                           \
    PF;                                                                         \
    u64 _sa = addx2(addx2(_a0, _a1), addx2(_a2, _a3));                          \
    u64 _sb = addx2(addx2(_b0, _b1), addx2(_b2, _b3));                          \
    float _d0l,_d0h,_d1l,_d1h; upk(_sa,_d0l,_d0h); upk(_sb,_d1l,_d1h);          \
    float _d0 = _d0l + _d0h, _d1 = _d1l + _d1h;                                 \
    float _A0 = fmaf(0.5f, tanh_ap(_d0), 0.5f);   /* i or f (sigmoid) */        \
    float _A1 = fmaf(m1,   tanh_ap(_d1), b1c);    /* g (tanh) or o (sigm) */    \
    float _B0 = __shfl_xor_sync(0xFFFFFFFFu, _A0, 1);                           \
    float _B1 = __shfl_xor_sync(0xFFFFFFFFu, _A1, 1);                           \
    float _tloc = _A0 * (p ? c : _A1);    /* p=1: F*c ; p=0: I*G */             \
    c = p ? fmaf(_B0, _B1, _tloc) : fmaf(_B0, c, _tloc);                        \
    float _O = p ? _A1 : _B1;                                                   \
    float _hn = _O * tanh_ap(c);                                                \
    if (valid) {                                                                \
        if (p == 0) (HW)[u] = _hn;                                              \
        else        *outp = _hn;                                                \
    }                                                                           \
    outp += OUTS;                                                               \
    __syncthreads();                                                            \
} while (0)

// ============================================================
// Kernel 2: layer-1 scan, 64 threads (2 warps), gate-pair layout.
// ============================================================
__global__ void __launch_bounds__(64, 1) k_scan1(
    const float* __restrict__ WhhF, const float* __restrict__ h0F, const float* __restrict__ c0F,
    const float* __restrict__ WhhB, const float* __restrict__ h0B, const float* __restrict__ c0B) {
    const bool bw = (blockIdx.x == 1);
    const float* Whh = bw ? WhhB : WhhF;
    const float* h0  = bw ? h0B  : h0F;
    const float* c0  = bw ? c0B  : c0F;
    const float* gx  = bw ? g_gx_bw1 : g_gx_fw1;
    const int off = bw ? H1 : 0;
    const int OUTS = D2;

    __shared__ __align__(16) float h_sh[2][32];

    const int tid = threadIdx.x;
    const int u = tid >> 1;
    const int p = tid & 1;
    const bool valid = (u < H1);
    const int uu = valid ? u : 0;
    // rows: p=0 -> (i_u, g_u); p=1 -> (f_u, o_u)   (PyTorch order i,f,g,o)
    const int r0 = p ? (H1 + uu)   : uu;            // f or i (sigmoid)
    const int r1 = p ? (3*H1 + uu) : (2*H1 + uu);   // o or g
    const float scl1 = p ? 0.5f : 1.f;               // o sigmoid / g tanh
    const float m1  = p ? 0.5f : 1.f;
    const float b1c = p ? 0.5f : 0.f;

    u64 wp0[16], wp1[16];
    #pragma unroll
    for (int k = 0; k < 15; k++) {
        wp0[k] = pk(valid ? 0.5f*Whh[r0*H1 + 2*k] : 0.f, valid ? 0.5f*Whh[r0*H1 + 2*k + 1] : 0.f);
        wp1[k] = pk(valid ? scl1*Whh[r1*H1 + 2*k] : 0.f, valid ? scl1*Whh[r1*H1 + 2*k + 1] : 0.f);
    }
    wp0[15] = pk(0.f, 0.f);
    wp1[15] = pk(0.f, 0.f);
    const u64 Z = pk(0.f, 0.f);

    if (tid < 32) {
        h_sh[0][tid] = (tid < H1) ? h0[tid] : 0.f;
        h_sh[1][tid] = 0.f;
    }
    float c = valid ? c0[uu] : 0.f;

    const int gbase = valid ? tid*2 : 0;            // (2u+p)*2, clamped
    float2 ga = *(const float2*)(gx + gbase);
    float2 gb = *(const float2*)(gx + G1 + gbase);
    const float2* pre = (const float2*)(gx + 2*G1 + gbase);
    float* outp = g_l1 + off + uu;
    __syncthreads();

    for (int t = 0; t < T - 2; t += 2) {
        { float2 gv = ga; PAIR_STEP(h_sh[0], h_sh[1], gv, 8, { ga = *pre; pre += G1/2; }); }
        { float2 gv = gb; PAIR_STEP(h_sh[1], h_sh[0], gv, 8, { gb = *pre; pre += G1/2; }); }
    }
    { float2 gv = ga; PAIR_STEP(h_sh[0], h_sh[1], gv, 8, {}); }
    { float2 gv = gb; PAIR_STEP(h_sh[1], h_sh[0], gv, 8, {}); }
}

// ============================================================
// Kernel 3: layer-2 input projections; writes paired layout,
// sigmoid rows pre-scaled by 0.5.
// ============================================================
#define GX2_BLOCKS 64
__global__ void __launch_bounds__(256) k_gx2(
    const float* __restrict__ WihF, const float* __restrict__ bF,
    const float* __restrict__ WihB, const float* __restrict__ bB) {
    __shared__ float W[D2 * G2];   // [k][j]
    __shared__ float row[D2];
    const bool bw = (blockIdx.y == 1);
    const float* Wih = bw ? WihB : WihF;
    const float* b   = bw ? bB   : bF;
    float* dst = bw ? g_gx_bw2 : g_gx_fw2;

    for (int i = threadIdx.x; i < G2*D2; i += blockDim.x) {
        int r = i / D2, k = i % D2;
        W[k*G2 + r] = Wih[i];
    }
    int jme = threadIdx.x;
    int gi = (jme < G2) ? (jme / H2) : 0;
    int uj = (jme < G2) ? (jme % H2) : 0;
    float bias = (jme < G2) ? b[jme] : 0.f;
    float scl = (gi == 2) ? 1.f : 0.5f;
    int dpos = uj*4 + gslot(gi);
    __syncthreads();

    const int tpb = T / GX2_BLOCKS;
    const int t0 = blockIdx.x * tpb;
    for (int t = t0; t < t0 + tpb; t++) {
        int src = bw ? (T-1-t) : t;
        __syncthreads();
        for (int i = threadIdx.x; i < D2; i += blockDim.x) row[i] = g_l1[(size_t)src*D2 + i];
        __syncthreads();
        if (jme < G2) {
            float acc = bias;
            #pragma unroll
            for (int k = 0; k < D2; k++) acc += W[k*G2 + jme] * row[k];
            dst[(size_t)t*G2 + dpos] = acc * scl;
        }
    }
}

// ============================================================
// Kernel 4: layer-2 scan, 128 threads (4 warps), gate-pair layout.
// ============================================================
__global__ void __launch_bounds__(128, 1) k_scan2(
    const float* __restrict__ WhhF, const float* __restrict__ h0F, const float* __restrict__ c0F,
    const float* __restrict__ WhhB, const float* __restrict__ h0B, const float* __restrict__ c0B) {
    const bool bw = (blockIdx.x == 1);
    const float* Whh = bw ? WhhB : WhhF;
    const float* h0  = bw ? h0B  : h0F;
    const float* c0  = bw ? c0B  : c0F;
    const float* gx  = bw ? g_gx_bw2 : g_gx_fw2;
    const int off = bw ? H2 : 0;
    const int OUTS = D3;

    __shared__ __align__(16) float h_sh[2][56];

    const int tid = threadIdx.x;
    const int u = tid >> 1;
    const int p = tid & 1;
    const bool valid = (u < H2);
    const int uu = valid ? u : 0;
    const int r0 = p ? (H2 + uu)   : uu;            // f or i (sigmoid)
    const int r1 = p ? (3*H2 + uu) : (2*H2 + uu);   // o or g
    const float scl1 = p ? 0.5f : 1.f;
    const float m1  = p ? 0.5f : 1.f;
    const float b1c = p ? 0.5f : 0.f;

    u64 wp0[26], wp1[26];
    #pragma unroll
    for (int k = 0; k < 25; k++) {
        wp0[k] = pk(valid ? 0.5f*Whh[r0*H2 + 2*k] : 0.f, valid ? 0.5f*Whh[r0*H2 + 2*k + 1] : 0.f);
        wp1[k] = pk(valid ? scl1*Whh[r1*H2 + 2*k] : 0.f, valid ? scl1*Whh[r1*H2 + 2*k + 1] : 0.f);
    }
    wp0[25] = pk(0.f, 0.f);
    wp1[25] = pk(0.f, 0.f);
    const u64 Z = pk(0.f, 0.f);

    if (tid < 56) {
        h_sh[0][tid] = (tid < H2) ? h0[tid] : 0.f;
        h_sh[1][tid] = 0.f;
    }
    float c = valid ? c0[uu] : 0.f;

    const int gbase = valid ? tid*2 : 0;
    float2 ga = *(const float2*)(gx + gbase);
    float2 gb = *(const float2*)(gx + G2 + gbase);
    const float2* pre = (const float2*)(gx + 2*G2 + gbase);
    float* outp = g_l2 + off + uu;
    __syncthreads();

    for (int t = 0; t < T - 2; t += 2) {
        { float2 gv = ga; PAIR_STEP(h_sh[0], h_sh[1], gv, 13, { ga = *pre; pre += G2/2; }); }
        { float2 gv = gb; PAIR_STEP(h_sh[1], h_sh[0], gv, 13, { gb = *pre; pre += G2/2; }); }
    }
    { float2 gv = ga; PAIR_STEP(h_sh[0], h_sh[1], gv, 13, {}); }
    { float2 gv = gb; PAIR_STEP(h_sh[1], h_sh[0], gv, 13, {}); }
}

// ============================================================
// Kernel 5: final MLP (weights in dynamic shared).
// ============================================================
#define MLP_SMEM ((HL*D3 + NT*HL + D3 + HL) * 4)
__global__ void __launch_bounds__(320, 1) k_mlp(
    const float* __restrict__ W1, const float* __restrict__ b1,
    const float* __restrict__ W2, const float* __restrict__ b2,
    float* __restrict__ out) {
    extern __shared__ float sm[];
    float* W1s  = sm;
    float* W2s  = W1s + HL*D3;
    float* rowS = W2s + NT*HL;
    float* hidS = rowS + D3;

    int tid = threadIdx.x;
    for (int i = tid; i < HL*D3; i += blockDim.x) W1s[i] = W1[i];
    for (int i = tid; i < NT*HL; i += blockDim.x) W2s[i] = W2[i];
    __syncthreads();

    for (int t = blockIdx.x; t < T; t += gridDim.x) {
        if (tid < D3) rowS[tid] = g_l2[(size_t)t*D3 + tid];
        __syncthreads();
        if (tid < HL) {
            float acc = b1[tid];
            const float4* wr = (const float4*)(W1s + tid*D3);
            const float4* r4 = (const float4*)rowS;
            #pragma unroll
            for (int k = 0; k < D3/4; k++) {
                float4 wv = wr[k]; float4 rv = r4[k];
                acc += wv.x*rv.x + wv.y*rv.y + wv.z*rv.z + wv.w*rv.w;
            }
            hidS[tid] = tanhf(acc);
        }
        __syncthreads();
        if (tid < NT) {
            float acc = b2[tid];
            const float4* wr = (const float4*)(W2s + tid*HL);
            const float4* h4 = (const float4*)hidS;
            #pragma unroll
            for (int k = 0; k < HL/4; k++) {
                float4 wv = wr[k]; float4 hv = h4[k];
                acc += wv.x*hv.x + wv.y*hv.y + wv.z*hv.z + wv.w*hv.w;
            }
            out[(size_t)t*NT + tid] = acc;
        }
        __syncthreads();
    }
}

// ============================================================
// launch
// ============================================================
extern "C" void kernel_launch(void* const* d_in, const int* in_sizes, int n_in,
                              void* d_out, int out_size) {
    const int*   x   = (const int*)  d_in[0];
    const float* emb = (const float*)d_in[1];

    const float* fw1_Wih = (const float*)d_in[2];
    const float* fw1_Whh = (const float*)d_in[3];
    const float* fw1_b   = (const float*)d_in[4];
    const float* fw1_h0  = (const float*)d_in[5];
    const float* fw1_c0  = (const float*)d_in[6];

    const float* bw1_Wih = (const float*)d_in[7];
    const float* bw1_Whh = (const float*)d_in[8];
    const float* bw1_b   = (const float*)d_in[9];
    const float* bw1_h0  = (const float*)d_in[10];
    const float* bw1_c0  = (const float*)d_in[11];

    const float* fw2_Wih = (const float*)d_in[12];
    const float* fw2_Whh = (const float*)d_in[13];
    const float* fw2_b   = (const float*)d_in[14];
    const float* fw2_h0  = (const float*)d_in[15];
    const float* fw2_c0  = (const float*)d_in[16];

    const float* bw2_Wih = (const float*)d_in[17];
    const float* bw2_Whh = (const float*)d_in[18];
    const float* bw2_b   = (const float*)d_in[19];
    const float* bw2_h0  = (const float*)d_in[20];
    const float* bw2_c0  = (const float*)d_in[21];

    const float* lin1_W = (const float*)d_in[22];
    const float* lin1_b = (const float*)d_in[23];
    const float* lin2_W = (const float*)d_in[24];
    const float* lin2_b = (const float*)d_in[25];

    cudaFuncSetAttribute(k_mlp, cudaFuncAttributeMaxDynamicSharedMemorySize, MLP_SMEM);

    k_gx1<<<T, 128>>>(x, emb, fw1_Wih, fw1_b, bw1_Wih, bw1_b);
    k_scan1<<<2, 64>>>(fw1_Whh, fw1_h0, fw1_c0, bw1_Whh, bw1_h0, bw1_c0);
    k_gx2<<<dim3(GX2_BLOCKS, 2), 256>>>(fw2_Wih, fw2_b, bw2_Wih, bw2_b);
    k_scan2<<<2, 128>>>(fw2_Whh, fw2_h0, fw2_c0, bw2_Whh, bw2_h0, bw2_c0);
    k_mlp<<<148, 320, MLP_SMEM>>>(lin1_W, lin1_b, lin2_W, lin2_b, (float*)d_out);
}

// round 10
// speedup vs baseline: 1.6904x; 1.0114x over previous
#include <cuda_runtime.h>
#include <cuda_bf16.h>
#include <math.h>

#define T  8192
#define E  20
#define H1 30
#define H2 50
#define HL 300
#define NT 50
#define G1 (4*H1)   // 120
#define G2 (4*H2)   // 200
#define D2 (2*H1)   // 60
#define D3 (2*H2)   // 100

// ---- scratch (no allocations allowed) ----
__device__ float g_gx_fw1[T*G1];
__device__ float g_gx_bw1[T*G1];
__device__ float g_l1[T*D2];
__device__ float g_gx_fw2[T*G2];
__device__ float g_gx_bw2[T*G2];
__device__ float g_l2[T*D3];

typedef unsigned long long u64;

__device__ __forceinline__ u64 pk(float lo, float hi) {
    u64 r; asm("mov.b64 %0, {%1, %2};" : "=l"(r) : "f"(lo), "f"(hi)); return r;
}
__device__ __forceinline__ void upk(u64 v, float& lo, float& hi) {
    asm("mov.b64 {%0, %1}, %2;" : "=f"(lo), "=f"(hi) : "l"(v));
}
__device__ __forceinline__ u64 ffma2(u64 a, u64 b, u64 c) {
    u64 d; asm("fma.rn.f32x2 %0, %1, %2, %3;" : "=l"(d) : "l"(a), "l"(b), "l"(c)); return d;
}
__device__ __forceinline__ u64 addx2(u64 a, u64 b) {
    u64 d; asm("add.rn.f32x2 %0, %1, %2;" : "=l"(d) : "l"(a), "l"(b)); return d;
}
__device__ __forceinline__ float tanh_ap(float x) {
    float y; asm("tanh.approx.f32 %0, %1;" : "=f"(y) : "f"(x)); return y;
}

// One LSTM step for the (unit, gate-pair) layout (scan1).
#define LSTM_STEP(HR, HW, GC0, GC1, NHALF, WP0, WP1, OUTP, OUTSTRIDE) do {            \
    const ulonglong2* _h8 = (const ulonglong2*)(HR);                                   \
    u64 _a0 = pk((GC0), 0.f), _a1 = Z, _a2 = Z, _a3 = Z;                               \
    u64 _b0 = pk((GC1), 0.f), _b1 = Z, _b2 = Z, _b3 = Z;                               \
    _Pragma("unroll")                                                                  \
    for (int _kk = 0; _kk < (NHALF); _kk++) {                                          \
        ulonglong2 _hv = _h8[_kk];                                                     \
        if ((_kk & 1) == 0) {                                                          \
            _a0 = ffma2((WP0)[2*_kk],   _hv.x, _a0);                                   \
            _a1 = ffma2((WP0)[2*_kk+1], _hv.y, _a1);                                   \
            _b0 = ffma2((WP1)[2*_kk],   _hv.x, _b0);                                   \
            _b1 = ffma2((WP1)[2*_kk+1], _hv.y, _b1);                                   \
        } else {                                                                       \
            _a2 = ffma2((WP0)[2*_kk],   _hv.x, _a2);                                   \
            _a3 = ffma2((WP0)[2*_kk+1], _hv.y, _a3);                                   \
            _b2 = ffma2((WP1)[2*_kk],   _hv.x, _b2);                                   \
            _b3 = ffma2((WP1)[2*_kk+1], _hv.y, _b3);                                   \
        }                                                                              \
    }                                                                                  \
    u64 _sa = addx2(addx2(_a0, _a1), addx2(_a2, _a3));                                 \
    u64 _sb = addx2(addx2(_b0, _b1), addx2(_b2, _b3));                                 \
    float _d0l,_d0h,_d1l,_d1h; upk(_sa,_d0l,_d0h); upk(_sb,_d1l,_d1h);                 \
    float _d0 = _d0l + _d0h, _d1 = _d1l + _d1h;                                        \
    float _A0 = fmaf(m0,   tanh_ap(s0*_d0),   b0c);                                    \
    float _A1 = fmaf(0.5f, tanh_ap(0.5f*_d1), 0.5f);                                   \
    float _B0 = __shfl_xor_sync(0xFFFFFFFFu, _A0, 1);                                  \
    float _B1 = __shfl_xor_sync(0xFFFFFFFFu, _A1, 1);                                  \
    float _I = p ? _B0 : _A0;                                                          \
    float _F = p ? _B1 : _A1;                                                          \
    float _G = p ? _A0 : _B0;                                                          \
    float _O = p ? _A1 : _B1;                                                          \
    c = fmaf(_F, c, _I*_G);                                                            \
    float _hn = _O * tanh_ap(c);                                                       \
    if (valid) {                                                                       \
        if (p == 0) (HW)[u] = _hn;                                                     \
        else        *(OUTP) = _hn;                                                     \
    }                                                                                  \
    (OUTP) += (OUTSTRIDE);                                                             \
    __syncthreads();                                                                   \
} while (0)

// ============================================================
// Kernel 1: embedding gather + layer-1 input projections.
// ============================================================
__global__ void k_gx1(const int* __restrict__ x, const float* __restrict__ emb,
                      const float* __restrict__ WihF, const float* __restrict__ bF,
                      const float* __restrict__ WihB, const float* __restrict__ bB) {
    __shared__ float e[E];
    int t = blockIdx.x;
    int j = threadIdx.x;
    if (j < E) e[j] = emb[(size_t)x[t] * E + j];
    __syncthreads();
    if (j < G1) {
        float aF = bF[j], aB = bB[j];
        #pragma unroll
        for (int k = 0; k < E; k++) {
            float ev = e[k];
            aF += WihF[j*E + k] * ev;
            aB += WihB[j*E + k] * ev;
        }
        g_gx_fw1[t*G1 + j] = aF;
        g_gx_bw1[(T-1-t)*G1 + j] = aB;
    }
}

// ============================================================
// Kernel 2: layer-1 scan (exact R5 best config).
// ============================================================
__global__ void __launch_bounds__(64, 1) k_scan1(
    const float* __restrict__ WhhF, const float* __restrict__ h0F, const float* __restrict__ c0F,
    const float* __restrict__ WhhB, const float* __restrict__ h0B, const float* __restrict__ c0B) {
    const bool bw = (blockIdx.x == 1);
    const float* Whh = bw ? WhhB : WhhF;
    const float* h0  = bw ? h0B  : h0F;
    const float* c0  = bw ? c0B  : c0F;
    const float* gx  = bw ? g_gx_bw1 : g_gx_fw1;
    const int off = bw ? H1 : 0;

    __shared__ __align__(16) float h_sh[2][32];

    const int tid = threadIdx.x;
    const int u = tid >> 1;
    const int p = tid & 1;
    const bool valid = (u < H1);
    const int uu = valid ? u : 0;
    const int r0 = p ? (2*H1 + uu) : uu;          // i or g
    const int r1 = p ? (3*H1 + uu) : (H1 + uu);   // f or o

    u64 wp0[16], wp1[16];
    #pragma unroll
    for (int k = 0; k < 15; k++) {
        wp0[k] = pk(valid ? Whh[r0*H1 + 2*k] : 0.f, valid ? Whh[r0*H1 + 2*k + 1] : 0.f);
        wp1[k] = pk(valid ? Whh[r1*H1 + 2*k] : 0.f, valid ? Whh[r1*H1 + 2*k + 1] : 0.f);
    }
    wp0[15] = pk(0.f, 0.f);
    wp1[15] = pk(0.f, 0.f);

    const float s0  = p ? 1.f : 0.5f;
    const float m0  = s0;
    const float b0c = p ? 0.f : 0.5f;
    const u64 Z = pk(0.f, 0.f);

    if (tid < 32) {
        h_sh[0][tid] = (tid < H1) ? h0[tid] : 0.f;
        h_sh[1][tid] = 0.f;
    }
    float c = valid ? c0[uu] : 0.f;

    float ga0 = valid ? gx[r0]      : 0.f;
    float ga1 = valid ? gx[r1]      : 0.f;
    float gb0 = valid ? gx[G1 + r0] : 0.f;
    float gb1 = valid ? gx[G1 + r1] : 0.f;
    const float* pre = gx + 2*G1;
    float* outp = g_l1 + off + uu;
    __syncthreads();

    for (int t = 0; t < T - 2; t += 2) {
        {
            float gc0 = ga0, gc1 = ga1;
            if (valid) { ga0 = pre[r0]; ga1 = pre[r1]; }
            pre += G1;
            LSTM_STEP(h_sh[0], h_sh[1], gc0, gc1, 8, wp0, wp1, outp, D2);
        }
        {
            float gc0 = gb0, gc1 = gb1;
            if (valid) { gb0 = pre[r0]; gb1 = pre[r1]; }
            pre += G1;
            LSTM_STEP(h_sh[1], h_sh[0], gc0, gc1, 8, wp0, wp1, outp, D2);
        }
    }
    LSTM_STEP(h_sh[0], h_sh[1], ga0, ga1, 8, wp0, wp1, outp, D2);
    LSTM_STEP(h_sh[1], h_sh[0], gb0, gb1, 8, wp0, wp1, outp, D2);
}

// ============================================================
// Kernel 3: layer-2 input projections (transposed W in shared).
// ============================================================
#define GX2_BLOCKS 64
__global__ void __launch_bounds__(256) k_gx2(
    const float* __restrict__ WihF, const float* __restrict__ bF,
    const float* __restrict__ WihB, const float* __restrict__ bB) {
    __shared__ float W[D2 * G2];   // [k][j]
    __shared__ float row[D2];
    const bool bw = (blockIdx.y == 1);
    const float* Wih = bw ? WihB : WihF;
    const float* b   = bw ? bB   : bF;
    float* dst = bw ? g_gx_bw2 : g_gx_fw2;

    for (int i = threadIdx.x; i < G2*D2; i += blockDim.x) {
        int r = i / D2, k = i % D2;
        W[k*G2 + r] = Wih[i];
    }
    float bias = (threadIdx.x < G2) ? b[threadIdx.x] : 0.f;
    __syncthreads();

    const int tpb = T / GX2_BLOCKS;
    const int t0 = blockIdx.x * tpb;
    for (int t = t0; t < t0 + tpb; t++) {
        int src = bw ? (T-1-t) : t;
        __syncthreads();
        for (int i = threadIdx.x; i < D2; i += blockDim.x) row[i] = g_l1[(size_t)src*D2 + i];
        __syncthreads();
        if (threadIdx.x < G2) {
            float acc = bias;
            #pragma unroll
            for (int k = 0; k < D2; k++) acc += W[k*G2 + threadIdx.x] * row[k];
            dst[(size_t)t*G2 + threadIdx.x] = acc;
        }
    }
}

// ============================================================
// Kernel 4: layer-2 scan, kh-SPLIT: 256 threads (8 warps, 2/SMSP).
// thread = u*4 + p*2 + kh: p = gate pair {i,f}/{g,o} as R5,
// kh = K-half. Each thread: 28 FFMA2 (half dot), then
// shfl_xor(1) to sum halves, shfl_xor(2) gate exchange (R5).
// ============================================================
__global__ void __launch_bounds__(256, 1) k_scan2(
    const float* __restrict__ WhhF, const float* __restrict__ h0F, const float* __restrict__ c0F,
    const float* __restrict__ WhhB, const float* __restrict__ h0B, const float* __restrict__ c0B) {
    const bool bw = (blockIdx.x == 1);
    const float* Whh = bw ? WhhB : WhhF;
    const float* h0  = bw ? h0B  : h0F;
    const float* c0  = bw ? c0B  : c0F;
    const float* gx  = bw ? g_gx_bw2 : g_gx_fw2;
    const int off = bw ? H2 : 0;

    __shared__ __align__(16) float h_sh[2][56];   // 14 ulonglong2 rows

    const int tid = threadIdx.x;
    const int u  = tid >> 2;
    const int p  = (tid >> 1) & 1;
    const int kh = tid & 1;
    const bool valid = (u < H2);
    const int uu = valid ? u : 0;
    const int r0 = p ? (2*H2 + uu) : uu;          // i or g
    const int r1 = p ? (3*H2 + uu) : (H2 + uu);   // f or o
    const int khb = kh * 7;                        // ulonglong2 base

    // weights for this K-half: 7 ulonglong2 slots = 14 u64 per row
    u64 wp0[14], wp1[14];
    #pragma unroll
    for (int kk = 0; kk < 7; kk++) {
        int base = (khb + kk) * 4;   // element index 0..55
        float a0 = (valid && base+0 < H2) ? Whh[r0*H2 + base+0] : 0.f;
        float a1 = (valid && base+1 < H2) ? Whh[r0*H2 + base+1] : 0.f;
        float a2 = (valid && base+2 < H2) ? Whh[r0*H2 + base+2] : 0.f;
        float a3 = (valid && base+3 < H2) ? Whh[r0*H2 + base+3] : 0.f;
        wp0[2*kk]   = pk(a0, a1);
        wp0[2*kk+1] = pk(a2, a3);
        float b0 = (valid && base+0 < H2) ? Whh[r1*H2 + base+0] : 0.f;
        float b1 = (valid && base+1 < H2) ? Whh[r1*H2 + base+1] : 0.f;
        float b2 = (valid && base+2 < H2) ? Whh[r1*H2 + base+2] : 0.f;
        float b3 = (valid && base+3 < H2) ? Whh[r1*H2 + base+3] : 0.f;
        wp1[2*kk]   = pk(b0, b1);
        wp1[2*kk+1] = pk(b2, b3);
    }

    const float s0  = p ? 1.f : 0.5f;
    const float m0  = s0;
    const float b0c = p ? 0.f : 0.5f;
    const u64 Z = pk(0.f, 0.f);

    if (tid < 56) {
        h_sh[0][tid] = (tid < H2) ? h0[tid] : 0.f;
        h_sh[1][tid] = 0.f;
    }
    float c = valid ? c0[uu] : 0.f;

    const bool gmask = valid && (kh == 0);   // gx added once per (u,p)
    float ga0 = gmask ? gx[r0]      : 0.f;
    float ga1 = gmask ? gx[r1]      : 0.f;
    float gb0 = gmask ? gx[G2 + r0] : 0.f;
    float gb1 = gmask ? gx[G2 + r1] : 0.f;
    const float* pre = gx + 2*G2;
    float* outp = g_l2 + off + uu;
    __syncthreads();

    #define KH_STEP(HR, HW, GC0, GC1) do {                                      \
        const ulonglong2* _h8 = ((const ulonglong2*)(HR)) + khb;                \
        u64 _a0 = pk((GC0), 0.f), _a1 = Z, _a2 = Z, _a3 = Z;                    \
        u64 _b0 = pk((GC1), 0.f), _b1 = Z, _b2 = Z, _b3 = Z;                    \
        _Pragma("unroll")                                                       \
        for (int _kk = 0; _kk < 7; _kk++) {                                     \
            ulonglong2 _hv = _h8[_kk];                                          \
            if ((_kk & 1) == 0) {                                               \
                _a0 = ffma2(wp0[2*_kk],   _hv.x, _a0);                          \
                _a1 = ffma2(wp0[2*_kk+1], _hv.y, _a1);                          \
                _b0 = ffma2(wp1[2*_kk],   _hv.x, _b0);                          \
                _b1 = ffma2(wp1[2*_kk+1], _hv.y, _b1);                          \
            } else {                                                            \
                _a2 = ffma2(wp0[2*_kk],   _hv.x, _a2);                          \
                _a3 = ffma2(wp0[2*_kk+1], _hv.y, _a3);                          \
                _b2 = ffma2(wp1[2*_kk],   _hv.x, _b2);                          \
                _b3 = ffma2(wp1[2*_kk+1], _hv.y, _b3);                          \
            }                                                                   \
        }                                                                       \
        u64 _sa = addx2(addx2(_a0, _a1), addx2(_a2, _a3));                      \
        u64 _sb = addx2(addx2(_b0, _b1), addx2(_b2, _b3));                      \
        float _d0l,_d0h,_d1l,_d1h; upk(_sa,_d0l,_d0h); upk(_sb,_d1l,_d1h);      \
        float _d0 = _d0l + _d0h, _d1 = _d1l + _d1h;                             \
        float _e0 = __shfl_xor_sync(0xFFFFFFFFu, _d0, 1);                       \
        float _e1 = __shfl_xor_sync(0xFFFFFFFFu, _d1, 1);                       \
        _d0 += _e0; _d1 += _e1;                                                 \
        float _A0 = fmaf(m0,   tanh_ap(s0*_d0),   b0c);                         \
        float _A1 = fmaf(0.5f, tanh_ap(0.5f*_d1), 0.5f);                        \
        float _B0 = __shfl_xor_sync(0xFFFFFFFFu, _A0, 2);                       \
        float _B1 = __shfl_xor_sync(0xFFFFFFFFu, _A1, 2);                       \
        float _I = p ? _B0 : _A0;                                               \
        float _F = p ? _B1 : _A1;                                               \
        float _G = p ? _A0 : _B0;                                               \
        float _O = p ? _A1 : _B1;                                               \
        c = fmaf(_F, c, _I*_G);                                                 \
        float _hn = _O * tanh_ap(c);                                            \
        if (valid && p == 0) {                                                  \
            if (kh == 0) (HW)[u] = _hn;                                         \
            else         *outp = _hn;                                           \
        }                                                                       \
        outp += D3;                                                             \
        __syncthreads();                                                        \
    } while (0)

    for (int t = 0; t < T - 2; t += 2) {
        {
            float gc0 = ga0, gc1 = ga1;
            if (gmask) { ga0 = pre[r0]; ga1 = pre[r1]; }
            pre += G2;
            KH_STEP(h_sh[0], h_sh[1], gc0, gc1);
        }
        {
            float gc0 = gb0, gc1 = gb1;
            if (gmask) { gb0 = pre[r0]; gb1 = pre[r1]; }
            pre += G2;
            KH_STEP(h_sh[1], h_sh[0], gc0, gc1);
        }
    }
    KH_STEP(h_sh[0], h_sh[1], ga0, ga1);
    KH_STEP(h_sh[1], h_sh[0], gb0, gb1);
    #undef KH_STEP
}

// ============================================================
// Kernel 5: final MLP (weights in dynamic shared).
// ============================================================
#define MLP_SMEM ((HL*D3 + NT*HL + D3 + HL) * 4)
__global__ void __launch_bounds__(320, 1) k_mlp(
    const float* __restrict__ W1, const float* __restrict__ b1,
    const float* __restrict__ W2, const float* __restrict__ b2,
    float* __restrict__ out) {
    extern __shared__ float sm[];
    float* W1s  = sm;
    float* W2s  = W1s + HL*D3;
    float* rowS = W2s + NT*HL;
    float* hidS = rowS + D3;

    int tid = threadIdx.x;
    for (int i = tid; i < HL*D3; i += blockDim.x) W1s[i] = W1[i];
    for (int i = tid; i < NT*HL; i += blockDim.x) W2s[i] = W2[i];
    __syncthreads();

    for (int t = blockIdx.x; t < T; t += gridDim.x) {
        if (tid < D3) rowS[tid] = g_l2[(size_t)t*D3 + tid];
        __syncthreads();
        if (tid < HL) {
            float acc = b1[tid];
            const float4* wr = (const float4*)(W1s + tid*D3);
            const float4* r4 = (const float4*)rowS;
            #pragma unroll
            for (int k = 0; k < D3/4; k++) {
                float4 wv = wr[k]; float4 rv = r4[k];
                acc += wv.x*rv.x + wv.y*rv.y + wv.z*rv.z + wv.w*rv.w;
            }
            hidS[tid] = tanhf(acc);
        }
        __syncthreads();
        if (tid < NT) {
            float acc = b2[tid];
            const float4* wr = (const float4*)(W2s + tid*HL);
            const float4* h4 = (const float4*)hidS;
            #pragma unroll
            for (int k = 0; k < HL/4; k++) {
                float4 wv = wr[k]; float4 hv = h4[k];
                acc += wv.x*hv.x + wv.y*hv.y + wv.z*hv.z + wv.w*hv.w;
            }
            out[(size_t)t*NT + tid] = acc;
        }
        __syncthreads();
    }
}

// ============================================================
// launch
// ============================================================
extern "C" void kernel_launch(void* const* d_in, const int* in_sizes, int n_in,
                              void* d_out, int out_size) {
    const int*   x   = (const int*)  d_in[0];
    const float* emb = (const float*)d_in[1];

    const float* fw1_Wih = (const float*)d_in[2];
    const float* fw1_Whh = (const float*)d_in[3];
    const float* fw1_b   = (const float*)d_in[4];
    const float* fw1_h0  = (const float*)d_in[5];
    const float* fw1_c0  = (const float*)d_in[6];

    const float* bw1_Wih = (const float*)d_in[7];
    const float* bw1_Whh = (const float*)d_in[8];
    const float* bw1_b   = (const float*)d_in[9];
    const float* bw1_h0  = (const float*)d_in[10];
    const float* bw1_c0  = (const float*)d_in[11];

    const float* fw2_Wih = (const float*)d_in[12];
    const float* fw2_Whh = (const float*)d_in[13];
    const float* fw2_b   = (const float*)d_in[14];
    const float* fw2_h0  = (const float*)d_in[15];
    const float* fw2_c0  = (const float*)d_in[16];

    const float* bw2_Wih = (const float*)d_in[17];
    const float* bw2_Whh = (const float*)d_in[18];
    const float* bw2_b   = (const float*)d_in[19];
    const float* bw2_h0  = (const float*)d_in[20];
    const float* bw2_c0  = (const float*)d_in[21];

    const float* lin1_W = (const float*)d_in[22];
    const float* lin1_b = (const float*)d_in[23];
    const float* lin2_W = (const float*)d_in[24];
    const float* lin2_b = (const float*)d_in[25];

    cudaFuncSetAttribute(k_mlp, cudaFuncAttributeMaxDynamicSharedMemorySize, MLP_SMEM);

    k_gx1<<<T, 128>>>(x, emb, fw1_Wih, fw1_b, bw1_Wih, bw1_b);
    k_scan1<<<2, 64>>>(fw1_Whh, fw1_h0, fw1_c0, bw1_Whh, bw1_h0, bw1_c0);
    k_gx2<<<dim3(GX2_BLOCKS, 2), 256>>>(fw2_Wih, fw2_b, bw2_Wih, bw2_b);
    k_scan2<<<2, 256>>>(fw2_Whh, fw2_h0, fw2_c0, bw2_Whh, bw2_h0, bw2_c0);
    k_mlp<<<148, 320, MLP_SMEM>>>(lin1_W, lin1_b, lin2_W, lin2_b, (float*)d_out);
}